// round 1
// baseline (speedup 1.0000x reference)
#include <cuda_runtime.h>

// RiskAwareMAE: mean over N of pinball-style loss
//   idx = nearest percentile bin of t (percentiles = linspace(0.01,1.0,100))
//   f   = (idx+1)/100
//   loss = max((f-1)*(t-o), f*(t-o)) = f*e + max(-e, 0)
//
// percentiles are uniform: p[i] = 0.01*(i+1). Nearest-with-tie-to-lower:
//   idx = clamp(ceil(100*t - 1.5), 0, 99)

#define NBLOCKS 1184   // 148 SMs * 8
#define NTHREADS 256

__device__ float g_partials[NBLOCKS];

__device__ __forceinline__ float loss_elem(float o, float t) {
    float fi = ceilf(fmaf(t, 100.0f, -1.5f));
    fi = fminf(fmaxf(fi, 0.0f), 99.0f);
    float f = (fi + 1.0f) * 0.01f;
    float e = t - o;
    // max((f-1)*e, f*e) = f*e + max(-e, 0)
    return fmaf(f, e, fmaxf(-e, 0.0f));
}

__device__ __forceinline__ float loss4(float4 o, float4 t) {
    return (loss_elem(o.x, t.x) + loss_elem(o.y, t.y)) +
           (loss_elem(o.z, t.z) + loss_elem(o.w, t.w));
}

__global__ void __launch_bounds__(NTHREADS)
partial_kernel(const float4* __restrict__ outs,
               const float4* __restrict__ tgts,
               int n4, int n_tail, const float* __restrict__ outs_s,
               const float* __restrict__ tgts_s) {
    const int tid = threadIdx.x;
    const int stride = NBLOCKS * NTHREADS;
    int i = blockIdx.x * NTHREADS + tid;

    float acc = 0.0f;

    // 4x unrolled main loop: 8 independent LDG.128 in flight per iteration
    for (; i + 3 * stride < n4; i += 4 * stride) {
        float4 o0 = outs[i];
        float4 o1 = outs[i + stride];
        float4 o2 = outs[i + 2 * stride];
        float4 o3 = outs[i + 3 * stride];
        float4 t0 = tgts[i];
        float4 t1 = tgts[i + stride];
        float4 t2 = tgts[i + 2 * stride];
        float4 t3 = tgts[i + 3 * stride];
        acc += loss4(o0, t0) + loss4(o1, t1);
        acc += loss4(o2, t2) + loss4(o3, t3);
    }
    for (; i < n4; i += stride) {
        acc += loss4(outs[i], tgts[i]);
    }

    // Scalar tail (N not divisible by 4) — handled by global thread 0 only.
    if (blockIdx.x == 0 && tid == 0) {
        for (int k = 0; k < n_tail; k++) {
            acc += loss_elem(outs_s[4 * n4 + k], tgts_s[4 * n4 + k]);
        }
    }

    // Warp reduction
    #pragma unroll
    for (int off = 16; off > 0; off >>= 1)
        acc += __shfl_xor_sync(0xFFFFFFFFu, acc, off);

    __shared__ float warp_sums[NTHREADS / 32];
    if ((tid & 31) == 0) warp_sums[tid >> 5] = acc;
    __syncthreads();

    if (tid < NTHREADS / 32) {
        float v = warp_sums[tid];
        #pragma unroll
        for (int off = (NTHREADS / 64); off > 0; off >>= 1)
            v += __shfl_xor_sync(0xFFFFFFFFu, v, off);
        if (tid == 0) g_partials[blockIdx.x] = v;
    }
}

__global__ void __launch_bounds__(256)
final_kernel(float* __restrict__ out, float inv_n) {
    const int tid = threadIdx.x;
    float acc = 0.0f;
    for (int i = tid; i < NBLOCKS; i += 256)
        acc += g_partials[i];

    #pragma unroll
    for (int off = 16; off > 0; off >>= 1)
        acc += __shfl_xor_sync(0xFFFFFFFFu, acc, off);

    __shared__ float warp_sums[8];
    if ((tid & 31) == 0) warp_sums[tid >> 5] = acc;
    __syncthreads();

    if (tid == 0) {
        float s = 0.0f;
        #pragma unroll
        for (int w = 0; w < 8; w++) s += warp_sums[w];
        out[0] = s * inv_n;
    }
}

extern "C" void kernel_launch(void* const* d_in, const int* in_sizes, int n_in,
                              void* d_out, int out_size) {
    const float* outs = (const float*)d_in[0];
    const float* tgts = (const float*)d_in[1];
    // d_in[2] = percentiles (linspace, handled analytically)
    float* out = (float*)d_out;

    const int n = in_sizes[0];
    const int n4 = n / 4;
    const int n_tail = n - 4 * n4;

    partial_kernel<<<NBLOCKS, NTHREADS>>>(
        (const float4*)outs, (const float4*)tgts, n4, n_tail, outs, tgts);
    final_kernel<<<1, 256>>>(out, 1.0f / (float)n);
}